// round 2
// baseline (speedup 1.0000x reference)
#include <cuda_runtime.h>

// Problem constants
constexpr int B_   = 4;
constexpr int T_   = 16;
constexpr int C_   = 256;
constexpr int HEADS = 8;
constexpr int DH   = 32;        // dim_head
constexpr int HW   = 1024;      // 32*32 spatial
constexpr int NSLAB = B_ * T_;  // 64 (b,t) slabs
constexpr float QSCALE = 0.17677669529663687f; // 32^-0.5

// Scratch (allocation-free: __device__ globals)
// q/k/v layout: [b][head][t][d][hw]  (hw contiguous)
__device__ float g_q[B_ * HEADS * T_ * DH * HW];
__device__ float g_k[B_ * HEADS * T_ * DH * HW];
__device__ float g_v[B_ * HEADS * T_ * DH * HW];
// attention output layout: [bt][e=head*32+d][hw]
__device__ float g_o[NSLAB * C_ * HW];

// ---------------- packed fp32x2 helpers (sm_100+) ----------------
__device__ __forceinline__ unsigned long long pack2(float lo, float hi) {
    unsigned long long r;
    asm("mov.b64 %0, {%1, %2};" : "=l"(r) : "f"(lo), "f"(hi));
    return r;
}
__device__ __forceinline__ void unpack2(unsigned long long p, float& lo, float& hi) {
    asm("mov.b64 {%0, %1}, %2;" : "=f"(lo), "=f"(hi) : "l"(p));
}
__device__ __forceinline__ unsigned long long ffma2(unsigned long long a,
                                                    unsigned long long b,
                                                    unsigned long long c) {
    unsigned long long d;
    asm("fma.rn.f32x2 %0, %1, %2, %3;" : "=l"(d) : "l"(a), "l"(b), "l"(c));
    return d;
}

// ---------------- GEMM: per-slab  Out[N,1024] = W[N,256] @ X[256,1024] ----------------
// Block tile: 128(n) x 128(m), BK=16, 256 threads, microtile 8(n) x 8(m).
// Per k-step per thread: 2 LDS.128 (A) + 2 LDS.128 (B) -> 32 FFMA2.
// EPI==0: QKV epilogue (route o -> q/k/v buffers, +bias, q*scale)
// EPI==1: plain epilogue (+bias) into Y (= d_out, already correct layout)
template <int EPI>
__global__ __launch_bounds__(256, 2) void gemm_k(const float* __restrict__ W,
                                                 const float* __restrict__ Xin,
                                                 const float* __restrict__ bias,
                                                 float* __restrict__ Y) {
    __shared__ __align__(16) float a_s[16][128];   // [k][n]
    __shared__ __align__(16) float b_s[16][128];   // [k][m]

    const int slab = blockIdx.z;          // bt = b*16 + t
    const int n0 = blockIdx.y * 128;
    const int m0 = blockIdx.x * 128;
    const int tid = threadIdx.x;
    const int tx = tid & 15;              // m group (8 m each)
    const int ty = tid >> 4;              // n group (8 n each)

    const float* Xs = (EPI == 1 ? (const float*)g_o : Xin) + (size_t)slab * C_ * HW;

    // global load mapping
    const int na = tid & 127;             // A row within tile (0..127)
    const int ka = (tid >> 7) * 8;        // 0 or 8
    const int kb = tid >> 4;              // 0..15
    const int mb = (tid & 15) * 8;        // 0..120
    const float* aptr = W + (size_t)(n0 + na) * C_ + ka;
    const float* bptr = Xs + (size_t)kb * HW + m0 + mb;

    unsigned long long acc[8][4];
#pragma unroll
    for (int r = 0; r < 8; r++)
#pragma unroll
        for (int p = 0; p < 4; p++) acc[r][p] = 0ull;

    float4 ra0 = *(const float4*)aptr;
    float4 ra1 = *(const float4*)(aptr + 4);
    float4 rb0 = *(const float4*)bptr;
    float4 rb1 = *(const float4*)(bptr + 4);

    for (int kt = 0; kt < 16; kt++) {
        // stage tiles (A transposed to [k][n])
        a_s[ka + 0][na] = ra0.x;
        a_s[ka + 1][na] = ra0.y;
        a_s[ka + 2][na] = ra0.z;
        a_s[ka + 3][na] = ra0.w;
        a_s[ka + 4][na] = ra1.x;
        a_s[ka + 5][na] = ra1.y;
        a_s[ka + 6][na] = ra1.z;
        a_s[ka + 7][na] = ra1.w;
        *(float4*)&b_s[kb][mb]     = rb0;
        *(float4*)&b_s[kb][mb + 4] = rb1;
        __syncthreads();

        if (kt < 15) {
            ra0 = *(const float4*)(aptr + (kt + 1) * 16);
            ra1 = *(const float4*)(aptr + (kt + 1) * 16 + 4);
            rb0 = *(const float4*)(bptr + (size_t)(kt + 1) * 16 * HW);
            rb1 = *(const float4*)(bptr + (size_t)(kt + 1) * 16 * HW + 4);
        }

#pragma unroll
        for (int k = 0; k < 16; k++) {
            const ulonglong2 bg0 = *(const ulonglong2*)&b_s[k][tx * 8];
            const ulonglong2 bg1 = *(const ulonglong2*)&b_s[k][tx * 8 + 4];
            const float4 ag0 = *(const float4*)&a_s[k][ty * 8];
            const float4 ag1 = *(const float4*)&a_s[k][ty * 8 + 4];
            const float av[8] = {ag0.x, ag0.y, ag0.z, ag0.w,
                                 ag1.x, ag1.y, ag1.z, ag1.w};
#pragma unroll
            for (int r = 0; r < 8; r++) {
                const unsigned long long aa = pack2(av[r], av[r]);
                acc[r][0] = ffma2(aa, bg0.x, acc[r][0]);
                acc[r][1] = ffma2(aa, bg0.y, acc[r][1]);
                acc[r][2] = ffma2(aa, bg1.x, acc[r][2]);
                acc[r][3] = ffma2(aa, bg1.y, acc[r][3]);
            }
        }
        __syncthreads();
    }

    // epilogue
    const int b_ = slab >> 4;   // b
    const int t_ = slab & 15;   // t
#pragma unroll
    for (int r = 0; r < 8; r++) {
        const int o = n0 + ty * 8 + r;
        float c0, c1, c2, c3, c4, c5, c6, c7;
        unpack2(acc[r][0], c0, c1);
        unpack2(acc[r][1], c2, c3);
        unpack2(acc[r][2], c4, c5);
        unpack2(acc[r][3], c6, c7);
        const float bv = bias[o];
        if (EPI == 0) {
            const int which = o >> 8;       // 0=q 1=k 2=v
            const int rem = o & 255;
            const int head = rem >> 5;
            const int d = rem & 31;
            float* dst;
            float sc = 1.0f;
            if (which == 0) { dst = g_q; sc = QSCALE; }
            else if (which == 1) { dst = g_k; }
            else { dst = g_v; }
            const size_t base =
                ((size_t)(((b_ * HEADS + head) * T_ + t_) * DH + d)) * HW + m0;
            float4 w0 = make_float4((c0 + bv) * sc, (c1 + bv) * sc,
                                    (c2 + bv) * sc, (c3 + bv) * sc);
            float4 w1 = make_float4((c4 + bv) * sc, (c5 + bv) * sc,
                                    (c6 + bv) * sc, (c7 + bv) * sc);
            *(float4*)(dst + base + tx * 8)     = w0;
            *(float4*)(dst + base + tx * 8 + 4) = w1;
        } else {
            float* dst = Y + ((size_t)slab * C_ + o) * HW + m0;
            float4 w0 = make_float4(c0 + bv, c1 + bv, c2 + bv, c3 + bv);
            float4 w1 = make_float4(c4 + bv, c5 + bv, c6 + bv, c7 + bv);
            *(float4*)(dst + tx * 8)     = w0;
            *(float4*)(dst + tx * 8 + 4) = w1;
        }
    }
}

// ---------------- Attention over T=16 per (b, head, hw) ----------------
// Block: one (b*8+head, hw tile of 8). 128 threads = 8(hw) x 16(i=query t).
// k/v staged in SMEM as [hw][t*32+d] (+4 float pad/row) so the d-loops read
// vectorized ulonglong2 (LDS.128) and accumulate with packed f32x2 FMAs.
constexpr int KVP = 512 + 4;  // padded row length
__global__ __launch_bounds__(128) void attn_k(const float* __restrict__ rel_pos) {
    __shared__ __align__(16) float k_s[8][KVP];
    __shared__ __align__(16) float v_s[8][KVP];

    const int bh  = blockIdx.y;            // b*8 + head
    const int hw0 = blockIdx.x * 8;
    const int tid = threadIdx.x;
    const int hwl = tid & 7;
    const int i   = tid >> 3;              // query time index 0..15

    const size_t ubase = (size_t)bh * 512 * HW;  // 512 = T*DH rows of 1024

    for (int e = tid; e < 4096; e += 128) {
        const int td = e >> 3;
        const int hw = e & 7;
        k_s[hw][td] = g_k[ubase + (size_t)td * HW + hw0 + hw];
        v_s[hw][td] = g_v[ubase + (size_t)td * HW + hw0 + hw];
    }
    __syncthreads();

    // q packed: qp[c] = (q[2c], q[2c+1])
    unsigned long long qp[16];
    const size_t qbase = ubase + (size_t)i * 32 * HW + hw0 + hwl;
#pragma unroll
    for (int c = 0; c < 16; c++)
        qp[c] = pack2(g_q[qbase + (size_t)(2 * c) * HW],
                      g_q[qbase + (size_t)(2 * c + 1) * HW]);

    const int head = bh & 7;
    const float* rp = rel_pos + head * 256 + i * 16;

    float s[16];
#pragma unroll
    for (int j = 0; j < 16; j++) {
        const ulonglong2* kp = (const ulonglong2*)&k_s[hwl][j * 32];
        unsigned long long acc = 0ull;
#pragma unroll
        for (int c = 0; c < 8; c++) {
            const ulonglong2 kk = kp[c];
            acc = ffma2(qp[2 * c],     kk.x, acc);
            acc = ffma2(qp[2 * c + 1], kk.y, acc);
        }
        float lo, hi;
        unpack2(acc, lo, hi);
        s[j] = lo + hi + rp[j];
    }

    float mx = s[0];
#pragma unroll
    for (int j = 1; j < 16; j++) mx = fmaxf(mx, s[j]);
    float sum = 0.0f;
#pragma unroll
    for (int j = 0; j < 16; j++) { s[j] = expf(s[j] - mx); sum += s[j]; }
    const float inv = 1.0f / sum;

    unsigned long long o2[16];
#pragma unroll
    for (int c = 0; c < 16; c++) o2[c] = 0ull;
#pragma unroll
    for (int j = 0; j < 16; j++) {
        const unsigned long long pp = pack2(s[j], s[j]);
        const ulonglong2* vp = (const ulonglong2*)&v_s[hwl][j * 32];
#pragma unroll
        for (int c = 0; c < 8; c++) {
            const ulonglong2 vv = vp[c];
            o2[2 * c]     = ffma2(pp, vv.x, o2[2 * c]);
            o2[2 * c + 1] = ffma2(pp, vv.y, o2[2 * c + 1]);
        }
    }

    const int b_ = bh >> 3;
    const size_t obase =
        ((size_t)((b_ * 16 + i) * 256 + head * 32)) * HW + hw0 + hwl;
#pragma unroll
    for (int c = 0; c < 16; c++) {
        float lo, hi;
        unpack2(o2[c], lo, hi);
        g_o[obase + (size_t)(2 * c) * HW]     = lo * inv;
        g_o[obase + (size_t)(2 * c + 1) * HW] = hi * inv;
    }
}

extern "C" void kernel_launch(void* const* d_in, const int* in_sizes, int n_in,
                              void* d_out, int out_size) {
    const float* x       = (const float*)d_in[0];
    const float* rel_pos = (const float*)d_in[1];
    const float* w_qkv   = (const float*)d_in[2];
    const float* b_qkv   = (const float*)d_in[3];
    const float* w_out   = (const float*)d_in[4];
    const float* b_out   = (const float*)d_in[5];
    float* y = (float*)d_out;

    // QKV projection: 64 slabs, N=768 (6 n-tiles), M=1024 (8 m-tiles)
    gemm_k<0><<<dim3(8, 6, 64), 256>>>(w_qkv, x, b_qkv, nullptr);
    // attention: grid (hw tiles=128, b*heads=32)
    attn_k<<<dim3(128, 32), 128>>>(rel_pos);
    // output projection: N=256 (2 n-tiles) -> y in (B,T,C,H,W) layout
    gemm_k<1><<<dim3(8, 2, 64), 256>>>(w_out, nullptr, b_out, y);
}

// round 4
// speedup vs baseline: 1.6396x; 1.6396x over previous
#include <cuda_runtime.h>
#include <cuda_fp16.h>
#include <cstdint>

// ---------------- problem constants ----------------
constexpr int B_    = 4;
constexpr int T_    = 16;
constexpr int C_    = 256;
constexpr int HEADS = 8;
constexpr int DH    = 32;
constexpr int HW    = 1024;       // 32*32
constexpr int NSLAB = B_ * T_;    // 64
constexpr float QSCALE = 0.17677669529663687f;

// ---------------- scratch (__device__ globals) ----------------
__device__ __half g_xhi[NSLAB * HW * C_];   // [slab][hw][c]
__device__ __half g_xlo[NSLAB * HW * C_];
__device__ __half g_whi[768 * 256];         // [o][c]
__device__ __half g_wlo[768 * 256];
__device__ __half g_wohi[256 * 256];
__device__ __half g_wolo[256 * 256];
__device__ float g_q[B_ * HEADS * T_ * DH * HW];   // [b][head][t][d][hw]
__device__ float g_k[B_ * HEADS * T_ * DH * HW];
__device__ float g_v[B_ * HEADS * T_ * DH * HW];
__device__ __half g_ohi[NSLAB * HW * C_];   // [slab][hw][e]
__device__ __half g_olo[NSLAB * HW * C_];

// ---------------- PTX helpers ----------------
__device__ __forceinline__ uint32_t smem_u32(const void* p) {
    uint32_t a;
    asm("{ .reg .u64 t; cvta.to.shared.u64 t, %1; cvt.u32.u64 %0, t; }" : "=r"(a) : "l"(p));
    return a;
}
__device__ __forceinline__ void cp16(uint32_t s, const void* g) {
    asm volatile("cp.async.cg.shared.global [%0], [%1], 16;" :: "r"(s), "l"(g) : "memory");
}
__device__ __forceinline__ void cp_commit() {
    asm volatile("cp.async.commit_group;" ::: "memory");
}
template <int N>
__device__ __forceinline__ void cp_wait() {
    asm volatile("cp.async.wait_group %0;" :: "n"(N) : "memory");
}
__device__ __forceinline__ void ldsm4(uint32_t& r0, uint32_t& r1, uint32_t& r2,
                                      uint32_t& r3, uint32_t a) {
    asm volatile("ldmatrix.sync.aligned.m8n8.x4.shared.b16 {%0,%1,%2,%3}, [%4];"
                 : "=r"(r0), "=r"(r1), "=r"(r2), "=r"(r3) : "r"(a));
}
__device__ __forceinline__ void mma16816(float& c0, float& c1, float& c2, float& c3,
                                         uint32_t a0, uint32_t a1, uint32_t a2,
                                         uint32_t a3, uint32_t b0, uint32_t b1) {
    asm volatile(
        "mma.sync.aligned.m16n8k16.row.col.f32.f16.f16.f32 "
        "{%0,%1,%2,%3}, {%4,%5,%6,%7}, {%8,%9}, {%0,%1,%2,%3};"
        : "+f"(c0), "+f"(c1), "+f"(c2), "+f"(c3)
        : "r"(a0), "r"(a1), "r"(a2), "r"(a3), "r"(b0), "r"(b1));
}

// ---------------- SMEM staging layout ----------------
// per chunk: A/B tiles, 128 rows x 32 halves, padded row stride 40 halves (80B)
constexpr int RSB   = 80;                  // padded row stride (bytes)
constexpr int TILEB = 128 * RSB;           // 10240 bytes per operand tile
constexpr int O_AHI = 0;
constexpr int O_ALO = TILEB;
constexpr int O_BHI = 2 * TILEB;
constexpr int O_BLO = 3 * TILEB;
constexpr int STAGE = 4 * TILEB;           // 40960
constexpr int SMEM_TOTAL = 2 * STAGE;      // 81920 (epilogue C reuses this)
constexpr int CSTR = 132;                  // C smem row stride (floats)

// ================= tensor-core GEMM =================
// D[hw 128, o 128] = A[hw, K] * B[o, K]^T, K=256, fp16 hi/lo 3-term split.
// EPI 0: QKV epilogue -> g_q/g_k/g_v. EPI 1: +bias -> Y [slab][c][hw].
template <int EPI>
__global__ __launch_bounds__(256) void mma_gemm(const __half* __restrict__ Ahig,
                                                const __half* __restrict__ Alog,
                                                const __half* __restrict__ Bhig,
                                                const __half* __restrict__ Blog,
                                                const float* __restrict__ bias,
                                                float* __restrict__ Y) {
    extern __shared__ char smem[];
    const uint32_t sb = smem_u32(smem);
    const int tid  = threadIdx.x;
    const int wid  = tid >> 5;
    const int lane = tid & 31;
    const int wm = wid & 1;     // warp m tile (64 rows)
    const int wn = wid >> 1;    // warp n tile (32 cols)

    const int slab = blockIdx.z;
    const int hw0  = blockIdx.x * 128;
    const int n0   = blockIdx.y * 128;

    const __half* ah = Ahig + ((size_t)slab * HW + hw0) * 256;
    const __half* al = Alog + ((size_t)slab * HW + hw0) * 256;
    const __half* bh = Bhig + (size_t)n0 * 256;
    const __half* bl = Blog + (size_t)n0 * 256;

    // ldmatrix lane address offsets (bytes)
    const uint32_t a_off = (uint32_t)((wm * 64 + (lane & 15)) * RSB + (lane >> 4) * 16);
    const uint32_t b_off = (uint32_t)((wn * 32 + lane) * RSB);

    float acc[4][4][4];
#pragma unroll
    for (int mt = 0; mt < 4; mt++)
#pragma unroll
        for (int nt = 0; nt < 4; nt++)
#pragma unroll
            for (int r = 0; r < 4; r++) acc[mt][nt][r] = 0.0f;

    // stage chunk kt into stage s
    auto issue = [&](int kt, int s) {
        const uint32_t base = sb + s * STAGE;
        const int kbase = kt * 32;
#pragma unroll
        for (int v = tid; v < 512; v += 256) {
            const int row = v >> 2;
            const int seg = v & 3;
            const uint32_t so = (uint32_t)(row * RSB + seg * 16);
            const size_t go = (size_t)row * 256 + kbase + seg * 8;
            cp16(base + O_AHI + so, ah + go);
            cp16(base + O_ALO + so, al + go);
            cp16(base + O_BHI + so, bh + go);
            cp16(base + O_BLO + so, bl + go);
        }
    };

    issue(0, 0);
    cp_commit();

    for (int kt = 0; kt < 8; kt++) {
        if (kt < 7) {
            issue(kt + 1, (kt + 1) & 1);
            cp_commit();
            cp_wait<1>();
        } else {
            cp_wait<0>();
        }
        __syncthreads();

        const uint32_t base = sb + (kt & 1) * STAGE;
#pragma unroll
        for (int kk = 0; kk < 2; kk++) {
            const uint32_t kb = kk * 32;   // bytes (16 halves)
            uint32_t ahi[4][4], alo[4][4];
            uint32_t b0h[4], b1h[4], b0l[4], b1l[4];
#pragma unroll
            for (int mt = 0; mt < 4; mt++)
                ldsm4(ahi[mt][0], ahi[mt][1], ahi[mt][2], ahi[mt][3],
                      base + O_AHI + a_off + (uint32_t)(mt * 16 * RSB) + kb);
            ldsm4(b0h[0], b0h[1], b0h[2], b0h[3], base + O_BHI + b_off + kb);
            ldsm4(b1h[0], b1h[1], b1h[2], b1h[3], base + O_BHI + b_off + kb + 16);
#pragma unroll
            for (int mt = 0; mt < 4; mt++)
#pragma unroll
                for (int nt = 0; nt < 4; nt++)
                    mma16816(acc[mt][nt][0], acc[mt][nt][1], acc[mt][nt][2],
                             acc[mt][nt][3], ahi[mt][0], ahi[mt][1], ahi[mt][2],
                             ahi[mt][3], b0h[nt], b1h[nt]);

            ldsm4(b0l[0], b0l[1], b0l[2], b0l[3], base + O_BLO + b_off + kb);
            ldsm4(b1l[0], b1l[1], b1l[2], b1l[3], base + O_BLO + b_off + kb + 16);
#pragma unroll
            for (int mt = 0; mt < 4; mt++)
#pragma unroll
                for (int nt = 0; nt < 4; nt++)
                    mma16816(acc[mt][nt][0], acc[mt][nt][1], acc[mt][nt][2],
                             acc[mt][nt][3], ahi[mt][0], ahi[mt][1], ahi[mt][2],
                             ahi[mt][3], b0l[nt], b1l[nt]);

#pragma unroll
            for (int mt = 0; mt < 4; mt++)
                ldsm4(alo[mt][0], alo[mt][1], alo[mt][2], alo[mt][3],
                      base + O_ALO + a_off + (uint32_t)(mt * 16 * RSB) + kb);
#pragma unroll
            for (int mt = 0; mt < 4; mt++)
#pragma unroll
                for (int nt = 0; nt < 4; nt++)
                    mma16816(acc[mt][nt][0], acc[mt][nt][1], acc[mt][nt][2],
                             acc[mt][nt][3], alo[mt][0], alo[mt][1], alo[mt][2],
                             alo[mt][3], b0h[nt], b1h[nt]);
        }
        __syncthreads();
    }

    // ---------------- epilogue: transpose through SMEM ----------------
    float* cs = (float*)smem;   // [128 n][CSTR m]
#pragma unroll
    for (int mt = 0; mt < 4; mt++)
#pragma unroll
        for (int nt = 0; nt < 4; nt++) {
            const int n = wn * 32 + nt * 8 + (lane & 3) * 2;
            const int m = wm * 64 + mt * 16 + (lane >> 2);
            cs[n * CSTR + m]           = acc[mt][nt][0];
            cs[(n + 1) * CSTR + m]     = acc[mt][nt][1];
            cs[n * CSTR + m + 8]       = acc[mt][nt][2];
            cs[(n + 1) * CSTR + m + 8] = acc[mt][nt][3];
        }
    __syncthreads();

    const int b_ = slab >> 4, t_ = slab & 15;
#pragma unroll
    for (int r = 0; r < 16; r++) {
        const int n = wid * 16 + r;
        const int o = n0 + n;
        float4 v = *(const float4*)&cs[n * CSTR + lane * 4];
        const float bv = bias[o];
        if (EPI == 0) {
            const int which = o >> 8;
            const int head  = (o >> 5) & 7;
            const int d     = o & 31;
            float* dst = (which == 0) ? g_q : (which == 1 ? g_k : g_v);
            const float sc = (which == 0) ? QSCALE : 1.0f;
            v.x = (v.x + bv) * sc; v.y = (v.y + bv) * sc;
            v.z = (v.z + bv) * sc; v.w = (v.w + bv) * sc;
            const size_t off =
                ((size_t)(((b_ * 8 + head) * 16 + t_) * 32 + d)) * 1024 + hw0 + lane * 4;
            *(float4*)(dst + off) = v;
        } else {
            v.x += bv; v.y += bv; v.z += bv; v.w += bv;
            *(float4*)(Y + ((size_t)slab * 256 + o) * 1024 + hw0 + lane * 4) = v;
        }
    }
}

// ================= split / transpose kernels =================
__global__ __launch_bounds__(256) void split_k(const float* __restrict__ s,
                                               __half* __restrict__ hi,
                                               __half* __restrict__ lo, int n) {
    const int i = blockIdx.x * 256 + threadIdx.x;
    if (i < n) {
        const float f = s[i];
        const __half h = __float2half_rn(f);
        hi[i] = h;
        lo[i] = __float2half_rn(f - __half2float(h));
    }
}

// x [slab][c][hw] f32 -> g_xhi/g_xlo [slab][hw][c] fp16 split (64x64 tiles)
__global__ __launch_bounds__(256) void split_x_k(const float* __restrict__ x) {
    __shared__ float ts[64][65];
    const int slab = blockIdx.z;
    const int c0 = blockIdx.y * 64;
    const int h0 = blockIdx.x * 64;
    const int tid = threadIdx.x;
    const int r = tid >> 2;
    const int q4 = tid & 3;

    const float* src = x + ((size_t)slab * 256 + c0 + r) * 1024 + h0 + q4 * 16;
#pragma unroll
    for (int j = 0; j < 4; j++) {
        const float4 v = *(const float4*)(src + j * 4);
        ts[r][q4 * 16 + j * 4 + 0] = v.x;
        ts[r][q4 * 16 + j * 4 + 1] = v.y;
        ts[r][q4 * 16 + j * 4 + 2] = v.z;
        ts[r][q4 * 16 + j * 4 + 3] = v.w;
    }
    __syncthreads();

    __half hb[16], lb[16];
#pragma unroll
    for (int j = 0; j < 16; j++) {
        const float f = ts[q4 * 16 + j][r];
        const __half h = __float2half_rn(f);
        hb[j] = h;
        lb[j] = __float2half_rn(f - __half2float(h));
    }
    const size_t o = ((size_t)slab * 1024 + h0 + r) * 256 + c0 + q4 * 16;
    *(uint4*)(g_xhi + o)     = ((uint4*)hb)[0];
    *(uint4*)(g_xhi + o + 8) = ((uint4*)hb)[1];
    *(uint4*)(g_xlo + o)     = ((uint4*)lb)[0];
    *(uint4*)(g_xlo + o + 8) = ((uint4*)lb)[1];
}

// ================= attention (T=16), f32 in, fp16-split out =================
__device__ __forceinline__ unsigned long long pack2(float lo, float hi) {
    unsigned long long r;
    asm("mov.b64 %0, {%1, %2};" : "=l"(r) : "f"(lo), "f"(hi));
    return r;
}
__device__ __forceinline__ void unpack2(unsigned long long p, float& lo, float& hi) {
    asm("mov.b64 {%0, %1}, %2;" : "=f"(lo), "=f"(hi) : "l"(p));
}
__device__ __forceinline__ unsigned long long ffma2(unsigned long long a,
                                                    unsigned long long b,
                                                    unsigned long long c) {
    unsigned long long d;
    asm("fma.rn.f32x2 %0, %1, %2, %3;" : "=l"(d) : "l"(a), "l"(b), "l"(c));
    return d;
}

constexpr int KVP = 512 + 4;
__global__ __launch_bounds__(128) void attn_k(const float* __restrict__ rel_pos) {
    __shared__ __align__(16) float k_s[8][KVP];
    __shared__ __align__(16) float v_s[8][KVP];

    const int bh  = blockIdx.y;
    const int hw0 = blockIdx.x * 8;
    const int tid = threadIdx.x;
    const int hwl = tid & 7;
    const int i   = tid >> 3;

    const size_t ubase = (size_t)bh * 512 * HW;

    for (int e = tid; e < 4096; e += 128) {
        const int td = e >> 3;
        const int hw = e & 7;
        k_s[hw][td] = g_k[ubase + (size_t)td * HW + hw0 + hw];
        v_s[hw][td] = g_v[ubase + (size_t)td * HW + hw0 + hw];
    }
    __syncthreads();

    unsigned long long qp[16];
    const size_t qbase = ubase + (size_t)i * 32 * HW + hw0 + hwl;
#pragma unroll
    for (int c = 0; c < 16; c++)
        qp[c] = pack2(g_q[qbase + (size_t)(2 * c) * HW],
                      g_q[qbase + (size_t)(2 * c + 1) * HW]);

    const int head = bh & 7;
    const float* rp = rel_pos + head * 256 + i * 16;

    float s[16];
#pragma unroll
    for (int j = 0; j < 16; j++) {
        const ulonglong2* kp = (const ulonglong2*)&k_s[hwl][j * 32];
        unsigned long long acc = 0ull;
#pragma unroll
        for (int c = 0; c < 8; c++) {
            const ulonglong2 kk = kp[c];
            acc = ffma2(qp[2 * c],     kk.x, acc);
            acc = ffma2(qp[2 * c + 1], kk.y, acc);
        }
        float lo, hi;
        unpack2(acc, lo, hi);
        s[j] = lo + hi + rp[j];
    }

    float mx = s[0];
#pragma unroll
    for (int j = 1; j < 16; j++) mx = fmaxf(mx, s[j]);
    float sum = 0.0f;
#pragma unroll
    for (int j = 0; j < 16; j++) { s[j] = expf(s[j] - mx); sum += s[j]; }
    const float inv = 1.0f / sum;

    unsigned long long o2[16];
#pragma unroll
    for (int c = 0; c < 16; c++) o2[c] = 0ull;
#pragma unroll
    for (int j = 0; j < 16; j++) {
        const unsigned long long pp = pack2(s[j], s[j]);
        const ulonglong2* vp = (const ulonglong2*)&v_s[hwl][j * 32];
#pragma unroll
        for (int c = 0; c < 8; c++) {
            const ulonglong2 vv = vp[c];
            o2[2 * c]     = ffma2(pp, vv.x, o2[2 * c]);
            o2[2 * c + 1] = ffma2(pp, vv.y, o2[2 * c + 1]);
        }
    }

    // write fp16-split output [slab][hw][e]
    const int b_ = bh >> 3;
    const size_t obase =
        ((size_t)((b_ * 16 + i)) * 1024 + hw0 + hwl) * 256 + head * 32;
#pragma unroll
    for (int c = 0; c < 16; c++) {
        float lo, hi;
        unpack2(o2[c], lo, hi);
        const float v0 = lo * inv, v1 = hi * inv;
        const __half h0 = __float2half_rn(v0);
        const __half h1 = __float2half_rn(v1);
        const __half l0 = __float2half_rn(v0 - __half2float(h0));
        const __half l1 = __float2half_rn(v1 - __half2float(h1));
        ((__half2*)(g_ohi + obase))[c] = __halves2half2(h0, h1);
        ((__half2*)(g_olo + obase))[c] = __halves2half2(l0, l1);
    }
}

// ================= host =================
extern "C" void kernel_launch(void* const* d_in, const int* in_sizes, int n_in,
                              void* d_out, int out_size) {
    const float* x       = (const float*)d_in[0];
    const float* rel_pos = (const float*)d_in[1];
    const float* w_qkv   = (const float*)d_in[2];
    const float* b_qkv   = (const float*)d_in[3];
    const float* w_out   = (const float*)d_in[4];
    const float* b_out   = (const float*)d_in[5];
    float* y = (float*)d_out;

    cudaFuncSetAttribute(mma_gemm<0>, cudaFuncAttributeMaxDynamicSharedMemorySize, SMEM_TOTAL);
    cudaFuncSetAttribute(mma_gemm<1>, cudaFuncAttributeMaxDynamicSharedMemorySize, SMEM_TOTAL);

    __half *xhi, *xlo, *whi, *wlo, *wohi, *wolo, *ohi, *olo;
    cudaGetSymbolAddress((void**)&xhi, g_xhi);
    cudaGetSymbolAddress((void**)&xlo, g_xlo);
    cudaGetSymbolAddress((void**)&whi, g_whi);
    cudaGetSymbolAddress((void**)&wlo, g_wlo);
    cudaGetSymbolAddress((void**)&wohi, g_wohi);
    cudaGetSymbolAddress((void**)&wolo, g_wolo);
    cudaGetSymbolAddress((void**)&ohi, g_ohi);
    cudaGetSymbolAddress((void**)&olo, g_olo);

    // precision splits
    split_k<<<768, 256>>>(w_qkv, whi, wlo, 768 * 256);
    split_k<<<256, 256>>>(w_out, wohi, wolo, 256 * 256);
    split_x_k<<<dim3(16, 4, 64), 256>>>(x);

    // QKV projection: grid = (hw tiles 8, o tiles 6, slabs 64)
    mma_gemm<0><<<dim3(8, 6, 64), 256, SMEM_TOTAL>>>(xhi, xlo, whi, wlo, b_qkv, nullptr);
    // attention
    attn_k<<<dim3(128, 32), 128>>>(rel_pos);
    // output projection: grid = (8, 2, 64)
    mma_gemm<1><<<dim3(8, 2, 64), 256, SMEM_TOTAL>>>(ohi, olo, wohi, wolo, b_out, y);
}

// round 6
// speedup vs baseline: 1.8522x; 1.1296x over previous
#include <cuda_runtime.h>
#include <cuda_fp16.h>
#include <cstdint>

// ---------------- problem constants ----------------
constexpr int B_    = 4;
constexpr int T_    = 16;
constexpr int C_    = 256;
constexpr int HEADS = 8;
constexpr int DH    = 32;
constexpr int HW    = 1024;       // 32*32
constexpr int NSLAB = B_ * T_;    // 64
constexpr float QSCALE = 0.17677669529663687f;

// ---------------- scratch (__device__ globals) ----------------
__device__ __half g_xhi[NSLAB * HW * C_];   // [slab][hw][c]
__device__ __half g_xlo[NSLAB * HW * C_];
__device__ __half g_whi[768 * 256];         // [o][c]
__device__ __half g_wlo[768 * 256];
__device__ __half g_wohi[256 * 256];
__device__ __half g_wolo[256 * 256];
__device__ float g_q[B_ * HEADS * T_ * DH * HW];   // [b][head][t][d][hw]
__device__ float g_k[B_ * HEADS * T_ * DH * HW];
__device__ float g_v[B_ * HEADS * T_ * DH * HW];
__device__ __half g_ohi[NSLAB * HW * C_];   // [slab][hw][e]
__device__ __half g_olo[NSLAB * HW * C_];

// ---------------- PTX helpers ----------------
__device__ __forceinline__ uint32_t smem_u32(const void* p) {
    uint32_t a;
    asm("{ .reg .u64 t; cvta.to.shared.u64 t, %1; cvt.u32.u64 %0, t; }" : "=r"(a) : "l"(p));
    return a;
}
__device__ __forceinline__ void cp16(uint32_t s, const void* g) {
    asm volatile("cp.async.cg.shared.global [%0], [%1], 16;" :: "r"(s), "l"(g) : "memory");
}
__device__ __forceinline__ void cp_commit() {
    asm volatile("cp.async.commit_group;" ::: "memory");
}
template <int N>
__device__ __forceinline__ void cp_wait() {
    asm volatile("cp.async.wait_group %0;" :: "n"(N) : "memory");
}
__device__ __forceinline__ void ldsm4(uint32_t& r0, uint32_t& r1, uint32_t& r2,
                                      uint32_t& r3, uint32_t a) {
    asm volatile("ldmatrix.sync.aligned.m8n8.x4.shared.b16 {%0,%1,%2,%3}, [%4];"
                 : "=r"(r0), "=r"(r1), "=r"(r2), "=r"(r3) : "r"(a));
}
__device__ __forceinline__ void mma16816(float& c0, float& c1, float& c2, float& c3,
                                         uint32_t a0, uint32_t a1, uint32_t a2,
                                         uint32_t a3, uint32_t b0, uint32_t b1) {
    asm volatile(
        "mma.sync.aligned.m16n8k16.row.col.f32.f16.f16.f32 "
        "{%0,%1,%2,%3}, {%4,%5,%6,%7}, {%8,%9}, {%0,%1,%2,%3};"
        : "+f"(c0), "+f"(c1), "+f"(c2), "+f"(c3)
        : "r"(a0), "r"(a1), "r"(a2), "r"(a3), "r"(b0), "r"(b1));
}

// ---------------- SMEM staging layout (swizzled, no padding) ----------------
// Row = 32 halves = 64B = 4 chunks of 16B. Chunk stored at (c ^ ((row>>1)&3)).
// A: 128 rows (8KB), B: 64 rows (4KB) per precision.
constexpr int O_AHI = 0;
constexpr int O_ALO = 8192;
constexpr int O_BHI = 16384;
constexpr int O_BLO = 20480;
constexpr int STAGE = 24576;
constexpr int SMEM_TOTAL = 2 * STAGE;       // 49152 (epilogue reuses)
constexpr int CSTR = 132;                   // C smem row stride (floats)

__device__ __forceinline__ uint32_t swz(int row, int chunk) {
    return (uint32_t)(row * 64 + ((chunk ^ ((row >> 1) & 3)) << 4));
}

// ================= tensor-core GEMM =================
// D[hw 128, o 64] = A[hw, K] * B[o, K]^T, K=256, fp16 hi/lo 3-term split.
// 128 threads, 4 warps (2m x 2n), warp tile 64x32, 2-stage cp.async, 4 CTAs/SM.
template <int EPI>
__global__ __launch_bounds__(128, 4) void mma_gemm(const __half* __restrict__ Ahig,
                                                   const __half* __restrict__ Alog,
                                                   const __half* __restrict__ Bhig,
                                                   const __half* __restrict__ Blog,
                                                   const float* __restrict__ bias,
                                                   float* __restrict__ Y) {
    extern __shared__ char smem[];
    const uint32_t sb = smem_u32(smem);
    const int tid  = threadIdx.x;
    const int wid  = tid >> 5;
    const int lane = tid & 31;
    const int wm = wid & 1;     // warp m tile (64 rows)
    const int wn = wid >> 1;    // warp n tile (32 cols)

    const int slab = blockIdx.z;
    const int hw0  = blockIdx.x * 128;
    const int n0   = blockIdx.y * 64;

    const __half* ah = Ahig + ((size_t)slab * HW + hw0) * 256;
    const __half* al = Alog + ((size_t)slab * HW + hw0) * 256;
    const __half* bh = Bhig + (size_t)n0 * 256;
    const __half* bl = Blog + (size_t)n0 * 256;

    // ldmatrix row/swizzle constants
    const int rowA0 = wm * 64 + (lane & 15);       // + mt*16
    const int chA   = lane >> 4;                   // 0/1, + 2*kk
    const int rowB  = wn * 32 + lane;
    const int rswB  = (rowB >> 1) & 3;

    float acc[4][4][4];
#pragma unroll
    for (int mt = 0; mt < 4; mt++)
#pragma unroll
        for (int nt = 0; nt < 4; nt++)
#pragma unroll
            for (int r = 0; r < 4; r++) acc[mt][nt][r] = 0.0f;

    // cp.async mapping: row rA (+32v), chunk sA
    const int rA = tid >> 2, sA = tid & 3;
    const int rswIO = (rA >> 1) & 3;               // (rA+32v)>>1 mod 4 invariant
    const uint32_t soIO = (uint32_t)(rA * 64 + ((sA ^ rswIO) << 4));

    auto issue = [&](int kt, int s) {
        const uint32_t base = sb + s * STAGE;
        const int kbase = kt * 32;
#pragma unroll
        for (int v = 0; v < 4; v++) {       // A rows rA + 32v
            const uint32_t so = soIO + (uint32_t)(v * 2048);
            const size_t go = (size_t)(rA + 32 * v) * 256 + kbase + sA * 8;
            cp16(base + O_AHI + so, ah + go);
            cp16(base + O_ALO + so, al + go);
        }
#pragma unroll
        for (int v = 0; v < 2; v++) {       // B rows rA + 32v
            const uint32_t so = soIO + (uint32_t)(v * 2048);
            const size_t go = (size_t)(rA + 32 * v) * 256 + kbase + sA * 8;
            cp16(base + O_BHI + so, bh + go);
            cp16(base + O_BLO + so, bl + go);
        }
    };

    issue(0, 0);
    cp_commit();

    for (int kt = 0; kt < 8; kt++) {
        if (kt < 7) {
            issue(kt + 1, (kt + 1) & 1);
            cp_commit();
            cp_wait<1>();
        } else {
            cp_wait<0>();
        }
        __syncthreads();

        const uint32_t base = sb + (kt & 1) * STAGE;
#pragma unroll
        for (int kk = 0; kk < 2; kk++) {
            uint32_t ahi[4][4], alo[4][4];
            uint32_t b0h[4], b1h[4], b0l[4], b1l[4];
#pragma unroll
            for (int mt = 0; mt < 4; mt++) {
                const int row = rowA0 + mt * 16;
                const uint32_t off = swz(row, chA + 2 * kk);
                ldsm4(ahi[mt][0], ahi[mt][1], ahi[mt][2], ahi[mt][3],
                      base + O_AHI + off);
            }
            {
                const uint32_t ob0 = (uint32_t)(rowB * 64 + (((2 * kk) ^ rswB) << 4));
                const uint32_t ob1 = (uint32_t)(rowB * 64 + (((2 * kk + 1) ^ rswB) << 4));
                ldsm4(b0h[0], b0h[1], b0h[2], b0h[3], base + O_BHI + ob0);
                ldsm4(b1h[0], b1h[1], b1h[2], b1h[3], base + O_BHI + ob1);
                ldsm4(b0l[0], b0l[1], b0l[2], b0l[3], base + O_BLO + ob0);
                ldsm4(b1l[0], b1l[1], b1l[2], b1l[3], base + O_BLO + ob1);
            }
#pragma unroll
            for (int mt = 0; mt < 4; mt++)
#pragma unroll
                for (int nt = 0; nt < 4; nt++)
                    mma16816(acc[mt][nt][0], acc[mt][nt][1], acc[mt][nt][2],
                             acc[mt][nt][3], ahi[mt][0], ahi[mt][1], ahi[mt][2],
                             ahi[mt][3], b0h[nt], b1h[nt]);
#pragma unroll
            for (int mt = 0; mt < 4; mt++)
#pragma unroll
                for (int nt = 0; nt < 4; nt++)
                    mma16816(acc[mt][nt][0], acc[mt][nt][1], acc[mt][nt][2],
                             acc[mt][nt][3], ahi[mt][0], ahi[mt][1], ahi[mt][2],
                             ahi[mt][3], b0l[nt], b1l[nt]);
#pragma unroll
            for (int mt = 0; mt < 4; mt++) {
                const int row = rowA0 + mt * 16;
                const uint32_t off = swz(row, chA + 2 * kk);
                ldsm4(alo[mt][0], alo[mt][1], alo[mt][2], alo[mt][3],
                      base + O_ALO + off);
            }
#pragma unroll
            for (int mt = 0; mt < 4; mt++)
#pragma unroll
                for (int nt = 0; nt < 4; nt++)
                    mma16816(acc[mt][nt][0], acc[mt][nt][1], acc[mt][nt][2],
                             acc[mt][nt][3], alo[mt][0], alo[mt][1], alo[mt][2],
                             alo[mt][3], b0h[nt], b1h[nt]);
        }
        __syncthreads();
    }

    // ---------------- epilogue: transpose through SMEM ----------------
    float* cs = (float*)smem;   // [64 n][CSTR m]
#pragma unroll
    for (int mt = 0; mt < 4; mt++)
#pragma unroll
        for (int nt = 0; nt < 4; nt++) {
            const int n = wn * 32 + nt * 8 + (lane & 3) * 2;
            const int m = wm * 64 + mt * 16 + (lane >> 2);
            cs[n * CSTR + m]           = acc[mt][nt][0];
            cs[(n + 1) * CSTR + m]     = acc[mt][nt][1];
            cs[n * CSTR + m + 8]       = acc[mt][nt][2];
            cs[(n + 1) * CSTR + m + 8] = acc[mt][nt][3];
        }
    __syncthreads();

    const int b_ = slab >> 4, t_ = slab & 15;
#pragma unroll
    for (int r = 0; r < 16; r++) {
        const int n = wid * 16 + r;
        const int o = n0 + n;
        float4 v = *(const float4*)&cs[n * CSTR + lane * 4];
        const float bv = bias[o];
        if (EPI == 0) {
            const int which = o >> 8;
            const int head  = (o >> 5) & 7;
            const int d     = o & 31;
            float* dst = (which == 0) ? g_q : (which == 1 ? g_k : g_v);
            const float sc = (which == 0) ? QSCALE : 1.0f;
            v.x = (v.x + bv) * sc; v.y = (v.y + bv) * sc;
            v.z = (v.z + bv) * sc; v.w = (v.w + bv) * sc;
            const size_t off =
                ((size_t)(((b_ * 8 + head) * 16 + t_) * 32 + d)) * 1024 + hw0 + lane * 4;
            *(float4*)(dst + off) = v;
        } else {
            v.x += bv; v.y += bv; v.z += bv; v.w += bv;
            *(float4*)(Y + ((size_t)slab * 256 + o) * 1024 + hw0 + lane * 4) = v;
        }
    }
}

// ================= split / transpose kernels =================
__global__ __launch_bounds__(256) void split_k(const float* __restrict__ s,
                                               __half* __restrict__ hi,
                                               __half* __restrict__ lo, int n) {
    const int i = blockIdx.x * 256 + threadIdx.x;
    if (i < n) {
        const float f = s[i];
        const __half h = __float2half_rn(f);
        hi[i] = h;
        lo[i] = __float2half_rn(f - __half2float(h));
    }
}

// x [slab][c][hw] f32 -> g_xhi/g_xlo [slab][hw][c] fp16 split (64x64 tiles)
__global__ __launch_bounds__(256) void split_x_k(const float* __restrict__ x) {
    __shared__ float ts[64][65];
    const int slab = blockIdx.z;
    const int c0 = blockIdx.y * 64;
    const int h0 = blockIdx.x * 64;
    const int tid = threadIdx.x;
    const int r = tid >> 2;
    const int q4 = tid & 3;

    const float* src = x + ((size_t)slab * 256 + c0 + r) * 1024 + h0 + q4 * 16;
#pragma unroll
    for (int j = 0; j < 4; j++) {
        const float4 v = *(const float4*)(src + j * 4);
        ts[r][q4 * 16 + j * 4 + 0] = v.x;
        ts[r][q4 * 16 + j * 4 + 1] = v.y;
        ts[r][q4 * 16 + j * 4 + 2] = v.z;
        ts[r][q4 * 16 + j * 4 + 3] = v.w;
    }
    __syncthreads();

    __half hb[16], lb[16];
#pragma unroll
    for (int j = 0; j < 16; j++) {
        const float f = ts[q4 * 16 + j][r];
        const __half h = __float2half_rn(f);
        hb[j] = h;
        lb[j] = __float2half_rn(f - __half2float(h));
    }
    const size_t o = ((size_t)slab * 1024 + h0 + r) * 256 + c0 + q4 * 16;
    *(uint4*)(g_xhi + o)     = ((uint4*)hb)[0];
    *(uint4*)(g_xhi + o + 8) = ((uint4*)hb)[1];
    *(uint4*)(g_xlo + o)     = ((uint4*)lb)[0];
    *(uint4*)(g_xlo + o + 8) = ((uint4*)lb)[1];
}

// ================= attention (T=16), f32 in, fp16-split out =================
__device__ __forceinline__ unsigned long long pack2(float lo, float hi) {
    unsigned long long r;
    asm("mov.b64 %0, {%1, %2};" : "=l"(r) : "f"(lo), "f"(hi));
    return r;
}
__device__ __forceinline__ void unpack2(unsigned long long p, float& lo, float& hi) {
    asm("mov.b64 {%0, %1}, %2;" : "=f"(lo), "=f"(hi) : "l"(p));
}
__device__ __forceinline__ unsigned long long ffma2(unsigned long long a,
                                                    unsigned long long b,
                                                    unsigned long long c) {
    unsigned long long d;
    asm("fma.rn.f32x2 %0, %1, %2, %3;" : "=l"(d) : "l"(a), "l"(b), "l"(c));
    return d;
}

constexpr int KVP = 512 + 4;
__global__ __launch_bounds__(128) void attn_k(const float* __restrict__ rel_pos) {
    __shared__ __align__(16) float k_s[8][KVP];
    __shared__ __align__(16) float v_s[8][KVP];

    const int bh  = blockIdx.y;
    const int hw0 = blockIdx.x * 8;
    const int tid = threadIdx.x;
    const int hwl = tid & 7;
    const int i   = tid >> 3;

    const size_t ubase = (size_t)bh * 512 * HW;

    for (int e = tid; e < 4096; e += 128) {
        const int td = e >> 3;
        const int hw = e & 7;
        k_s[hw][td] = g_k[ubase + (size_t)td * HW + hw0 + hw];
        v_s[hw][td] = g_v[ubase + (size_t)td * HW + hw0 + hw];
    }
    __syncthreads();

    unsigned long long qp[16];
    const size_t qbase = ubase + (size_t)i * 32 * HW + hw0 + hwl;
#pragma unroll
    for (int c = 0; c < 16; c++)
        qp[c] = pack2(g_q[qbase + (size_t)(2 * c) * HW],
                      g_q[qbase + (size_t)(2 * c + 1) * HW]);

    const int head = bh & 7;
    const float* rp = rel_pos + head * 256 + i * 16;

    float s[16];
#pragma unroll
    for (int j = 0; j < 16; j++) {
        const ulonglong2* kp = (const ulonglong2*)&k_s[hwl][j * 32];
        unsigned long long acc = 0ull;
#pragma unroll
        for (int c = 0; c < 8; c++) {
            const ulonglong2 kk = kp[c];
            acc = ffma2(qp[2 * c],     kk.x, acc);
            acc = ffma2(qp[2 * c + 1], kk.y, acc);
        }
        float lo, hi;
        unpack2(acc, lo, hi);
        s[j] = lo + hi + rp[j];
    }

    float mx = s[0];
#pragma unroll
    for (int j = 1; j < 16; j++) mx = fmaxf(mx, s[j]);
    float sum = 0.0f;
#pragma unroll
    for (int j = 0; j < 16; j++) { s[j] = expf(s[j] - mx); sum += s[j]; }
    const float inv = 1.0f / sum;

    unsigned long long o2[16];
#pragma unroll
    for (int c = 0; c < 16; c++) o2[c] = 0ull;
#pragma unroll
    for (int j = 0; j < 16; j++) {
        const unsigned long long pp = pack2(s[j], s[j]);
        const ulonglong2* vp = (const ulonglong2*)&v_s[hwl][j * 32];
#pragma unroll
        for (int c = 0; c < 8; c++) {
            const ulonglong2 vv = vp[c];
            o2[2 * c]     = ffma2(pp, vv.x, o2[2 * c]);
            o2[2 * c + 1] = ffma2(pp, vv.y, o2[2 * c + 1]);
        }
    }

    // write fp16-split output [slab][hw][e]
    const int b_ = bh >> 3;
    const size_t obase =
        ((size_t)((b_ * 16 + i)) * 1024 + hw0 + hwl) * 256 + head * 32;
#pragma unroll
    for (int c = 0; c < 16; c++) {
        float lo, hi;
        unpack2(o2[c], lo, hi);
        const float v0 = lo * inv, v1 = hi * inv;
        const __half h0 = __float2half_rn(v0);
        const __half h1 = __float2half_rn(v1);
        const __half l0 = __float2half_rn(v0 - __half2float(h0));
        const __half l1 = __float2half_rn(v1 - __half2float(h1));
        ((__half2*)(g_ohi + obase))[c] = __halves2half2(h0, h1);
        ((__half2*)(g_olo + obase))[c] = __halves2half2(l0, l1);
    }
}

// ================= host =================
extern "C" void kernel_launch(void* const* d_in, const int* in_sizes, int n_in,
                              void* d_out, int out_size) {
    const float* x       = (const float*)d_in[0];
    const float* rel_pos = (const float*)d_in[1];
    const float* w_qkv   = (const float*)d_in[2];
    const float* b_qkv   = (const float*)d_in[3];
    const float* w_out   = (const float*)d_in[4];
    const float* b_out   = (const float*)d_in[5];
    float* y = (float*)d_out;

    cudaFuncSetAttribute(mma_gemm<0>, cudaFuncAttributeMaxDynamicSharedMemorySize, SMEM_TOTAL);
    cudaFuncSetAttribute(mma_gemm<1>, cudaFuncAttributeMaxDynamicSharedMemorySize, SMEM_TOTAL);

    __half *xhi, *xlo, *whi, *wlo, *wohi, *wolo, *ohi, *olo;
    cudaGetSymbolAddress((void**)&xhi, g_xhi);
    cudaGetSymbolAddress((void**)&xlo, g_xlo);
    cudaGetSymbolAddress((void**)&whi, g_whi);
    cudaGetSymbolAddress((void**)&wlo, g_wlo);
    cudaGetSymbolAddress((void**)&wohi, g_wohi);
    cudaGetSymbolAddress((void**)&wolo, g_wolo);
    cudaGetSymbolAddress((void**)&ohi, g_ohi);
    cudaGetSymbolAddress((void**)&olo, g_olo);

    // precision splits
    split_k<<<768, 256>>>(w_qkv, whi, wlo, 768 * 256);
    split_k<<<256, 256>>>(w_out, wohi, wolo, 256 * 256);
    split_x_k<<<dim3(16, 4, 64), 256>>>(x);

    // QKV projection: grid = (hw tiles 8, o tiles 12, slabs 64)
    mma_gemm<0><<<dim3(8, 12, 64), 128, SMEM_TOTAL>>>(xhi, xlo, whi, wlo, b_qkv, nullptr);
    // attention
    attn_k<<<dim3(128, 32), 128>>>(rel_pos);
    // output projection: grid = (8, 4, 64)
    mma_gemm<1><<<dim3(8, 4, 64), 128, SMEM_TOTAL>>>(ohi, olo, wohi, wolo, b_out, y);
}

// round 7
// speedup vs baseline: 1.8748x; 1.0122x over previous
#include <cuda_runtime.h>
#include <cuda_fp16.h>
#include <cstdint>

// ---------------- problem constants ----------------
constexpr int B_    = 4;
constexpr int T_    = 16;
constexpr int C_    = 256;
constexpr int HEADS = 8;
constexpr int DH    = 32;
constexpr int HW    = 1024;       // 32*32
constexpr int NSLAB = B_ * T_;    // 64
constexpr float QSCALE = 0.17677669529663687f;

// ---------------- scratch (__device__ globals) ----------------
__device__ __half g_xhi[NSLAB * HW * C_];   // [slab][hw][c]
__device__ __half g_xlo[NSLAB * HW * C_];
__device__ __half g_whi[768 * 256];         // [o][c]
__device__ __half g_wlo[768 * 256];
__device__ __half g_wohi[256 * 256];
__device__ __half g_wolo[256 * 256];
__device__ float g_q[B_ * HEADS * T_ * DH * HW];   // [b][head][t][d][hw]
__device__ float g_k[B_ * HEADS * T_ * DH * HW];
__device__ float g_v[B_ * HEADS * T_ * DH * HW];
__device__ __half g_ohi[NSLAB * HW * C_];   // [slab][hw][e]
__device__ __half g_olo[NSLAB * HW * C_];

// ---------------- PTX helpers ----------------
__device__ __forceinline__ uint32_t smem_u32(const void* p) {
    uint32_t a;
    asm("{ .reg .u64 t; cvta.to.shared.u64 t, %1; cvt.u32.u64 %0, t; }" : "=r"(a) : "l"(p));
    return a;
}
__device__ __forceinline__ void cp16(uint32_t s, const void* g) {
    asm volatile("cp.async.cg.shared.global [%0], [%1], 16;" :: "r"(s), "l"(g) : "memory");
}
__device__ __forceinline__ void cp_commit() {
    asm volatile("cp.async.commit_group;" ::: "memory");
}
template <int N>
__device__ __forceinline__ void cp_wait() {
    asm volatile("cp.async.wait_group %0;" :: "n"(N) : "memory");
}
__device__ __forceinline__ void ldsm4(uint32_t& r0, uint32_t& r1, uint32_t& r2,
                                      uint32_t& r3, uint32_t a) {
    asm volatile("ldmatrix.sync.aligned.m8n8.x4.shared.b16 {%0,%1,%2,%3}, [%4];"
                 : "=r"(r0), "=r"(r1), "=r"(r2), "=r"(r3) : "r"(a));
}
__device__ __forceinline__ void mma16816(float& c0, float& c1, float& c2, float& c3,
                                         uint32_t a0, uint32_t a1, uint32_t a2,
                                         uint32_t a3, uint32_t b0, uint32_t b1) {
    asm volatile(
        "mma.sync.aligned.m16n8k16.row.col.f32.f16.f16.f32 "
        "{%0,%1,%2,%3}, {%4,%5,%6,%7}, {%8,%9}, {%0,%1,%2,%3};"
        : "+f"(c0), "+f"(c1), "+f"(c2), "+f"(c3)
        : "r"(a0), "r"(a1), "r"(a2), "r"(a3), "r"(b0), "r"(b1));
}

// ---------------- SMEM staging layout (swizzled, no padding) ----------------
// Row = 32 halves = 64B = 4 chunks of 16B. Chunk stored at (c ^ ((row>>1)&3)).
// A: 128 rows (8KB), B: 64 rows (4KB) per precision.
constexpr int O_AHI = 0;
constexpr int O_ALO = 8192;
constexpr int O_BHI = 16384;
constexpr int O_BLO = 20480;
constexpr int STAGE = 24576;
constexpr int SMEM_TOTAL = 2 * STAGE;       // 49152 (epilogue reuses)
constexpr int CSTR = 132;                   // C smem row stride (floats)

__device__ __forceinline__ uint32_t swz(int row, int chunk) {
    return (uint32_t)(row * 64 + ((chunk ^ ((row >> 1) & 3)) << 4));
}

// ================= tensor-core GEMM =================
// D[hw 128, o 64] = A[hw, K] * B[o, K]^T, K=256, fp16 hi/lo 3-term split.
// 128 threads, 4 warps (2m x 2n), warp tile 64x32, 2-stage cp.async, 4 CTAs/SM.
template <int EPI>
__global__ __launch_bounds__(128, 4) void mma_gemm(const __half* __restrict__ Ahig,
                                                   const __half* __restrict__ Alog,
                                                   const __half* __restrict__ Bhig,
                                                   const __half* __restrict__ Blog,
                                                   const float* __restrict__ bias,
                                                   float* __restrict__ Y) {
    extern __shared__ __align__(1024) char smem[];
    const uint32_t sb = smem_u32(smem);
    const int tid  = threadIdx.x;
    const int wid  = tid >> 5;
    const int lane = tid & 31;
    const int wm = wid & 1;     // warp m tile (64 rows)
    const int wn = wid >> 1;    // warp n tile (32 cols)

    const int slab = blockIdx.z;
    const int hw0  = blockIdx.x * 128;
    const int n0   = blockIdx.y * 64;

    const __half* ah = Ahig + ((size_t)slab * HW + hw0) * 256;
    const __half* al = Alog + ((size_t)slab * HW + hw0) * 256;
    const __half* bh = Bhig + (size_t)n0 * 256;
    const __half* bl = Blog + (size_t)n0 * 256;

    // ---- hoisted ldmatrix base addresses (kk=0, stage 0) ----
    // XOR-linearity of the swizzle: kk=1 -> ^0x20, B second frag -> ^0x10,
    // lo operand -> +(O_xLO-O_xHI), stage -> +STAGE (toggled via so^=STAGE).
    const int rowA0 = wm * 64 + (lane & 15);
    const int chA   = lane >> 4;
    const int rowB  = wn * 32 + lane;
    const uint32_t adrA[4] = {
        sb + O_AHI + swz(rowA0,      chA),
        sb + O_AHI + swz(rowA0 + 16, chA),
        sb + O_AHI + swz(rowA0 + 32, chA),
        sb + O_AHI + swz(rowA0 + 48, chA)};
    const uint32_t adrB = sb + O_BHI + swz(rowB, 0);

    float acc[4][4][4];
#pragma unroll
    for (int mt = 0; mt < 4; mt++)
#pragma unroll
        for (int nt = 0; nt < 4; nt++)
#pragma unroll
            for (int r = 0; r < 4; r++) acc[mt][nt][r] = 0.0f;

    // cp.async mapping: row rA (+32v), chunk sA
    const int rA = tid >> 2, sA = tid & 3;
    const int rswIO = (rA >> 1) & 3;
    const uint32_t soIO = (uint32_t)(rA * 64 + ((sA ^ rswIO) << 4));

    auto issue = [&](int kt, int s) {
        const uint32_t base = sb + s * STAGE;
        const int kbase = kt * 32;
#pragma unroll
        for (int v = 0; v < 4; v++) {       // A rows rA + 32v
            const uint32_t so = soIO + (uint32_t)(v * 2048);
            const size_t go = (size_t)(rA + 32 * v) * 256 + kbase + sA * 8;
            cp16(base + O_AHI + so, ah + go);
            cp16(base + O_ALO + so, al + go);
        }
#pragma unroll
        for (int v = 0; v < 2; v++) {       // B rows rA + 32v
            const uint32_t so = soIO + (uint32_t)(v * 2048);
            const size_t go = (size_t)(rA + 32 * v) * 256 + kbase + sA * 8;
            cp16(base + O_BHI + so, bh + go);
            cp16(base + O_BLO + so, bl + go);
        }
    };

    issue(0, 0);
    cp_commit();

    uint32_t so = 0;   // stage offset, toggles 0 <-> STAGE
    for (int kt = 0; kt < 8; kt++) {
        if (kt < 7) {
            issue(kt + 1, (kt + 1) & 1);
            cp_commit();
            cp_wait<1>();
        } else {
            cp_wait<0>();
        }
        __syncthreads();

#pragma unroll
        for (int kk = 0; kk < 2; kk++) {
            const uint32_t kx = (uint32_t)(kk << 5);   // kk=1 -> ^0x20
            uint32_t ahi[4][4], alo[4][4];
            uint32_t b0h[4], b1h[4], b0l[4], b1l[4];
            // all hi/b ldsm upfront so latency hides under the MMA burst
#pragma unroll
            for (int mt = 0; mt < 4; mt++)
                ldsm4(ahi[mt][0], ahi[mt][1], ahi[mt][2], ahi[mt][3],
                      (adrA[mt] ^ kx) + so);
            {
                const uint32_t bb = (adrB ^ kx) + so;
                ldsm4(b0h[0], b0h[1], b0h[2], b0h[3], bb);
                ldsm4(b1h[0], b1h[1], b1h[2], b1h[3], bb ^ 0x10);
                ldsm4(b0l[0], b0l[1], b0l[2], b0l[3], bb + 4096);
                ldsm4(b1l[0], b1l[1], b1l[2], b1l[3], (bb ^ 0x10) + 4096);
            }
#pragma unroll
            for (int mt = 0; mt < 4; mt++)
#pragma unroll
                for (int nt = 0; nt < 4; nt++)
                    mma16816(acc[mt][nt][0], acc[mt][nt][1], acc[mt][nt][2],
                             acc[mt][nt][3], ahi[mt][0], ahi[mt][1], ahi[mt][2],
                             ahi[mt][3], b0h[nt], b1h[nt]);
#pragma unroll
            for (int mt = 0; mt < 4; mt++)
                ldsm4(alo[mt][0], alo[mt][1], alo[mt][2], alo[mt][3],
                      (adrA[mt] ^ kx) + so + 8192);
#pragma unroll
            for (int mt = 0; mt < 4; mt++)
#pragma unroll
                for (int nt = 0; nt < 4; nt++)
                    mma16816(acc[mt][nt][0], acc[mt][nt][1], acc[mt][nt][2],
                             acc[mt][nt][3], ahi[mt][0], ahi[mt][1], ahi[mt][2],
                             ahi[mt][3], b0l[nt], b1l[nt]);
#pragma unroll
            for (int mt = 0; mt < 4; mt++)
#pragma unroll
                for (int nt = 0; nt < 4; nt++)
                    mma16816(acc[mt][nt][0], acc[mt][nt][1], acc[mt][nt][2],
                             acc[mt][nt][3], alo[mt][0], alo[mt][1], alo[mt][2],
                             alo[mt][3], b0h[nt], b1h[nt]);
        }
        __syncthreads();
        so ^= (uint32_t)STAGE;
    }

    // ---------------- epilogue: transpose through SMEM ----------------
    float* cs = (float*)smem;   // [64 n][CSTR m]
#pragma unroll
    for (int mt = 0; mt < 4; mt++)
#pragma unroll
        for (int nt = 0; nt < 4; nt++) {
            const int n = wn * 32 + nt * 8 + (lane & 3) * 2;
            const int m = wm * 64 + mt * 16 + (lane >> 2);
            cs[n * CSTR + m]           = acc[mt][nt][0];
            cs[(n + 1) * CSTR + m]     = acc[mt][nt][1];
            cs[n * CSTR + m + 8]       = acc[mt][nt][2];
            cs[(n + 1) * CSTR + m + 8] = acc[mt][nt][3];
        }
    __syncthreads();

    const int b_ = slab >> 4, t_ = slab & 15;
#pragma unroll
    for (int r = 0; r < 16; r++) {
        const int n = wid * 16 + r;
        const int o = n0 + n;
        float4 v = *(const float4*)&cs[n * CSTR + lane * 4];
        const float bv = bias[o];
        if (EPI == 0) {
            const int which = o >> 8;
            const int head  = (o >> 5) & 7;
            const int d     = o & 31;
            float* dst = (which == 0) ? g_q : (which == 1 ? g_k : g_v);
            const float sc = (which == 0) ? QSCALE : 1.0f;
            v.x = (v.x + bv) * sc; v.y = (v.y + bv) * sc;
            v.z = (v.z + bv) * sc; v.w = (v.w + bv) * sc;
            const size_t off =
                ((size_t)(((b_ * 8 + head) * 16 + t_) * 32 + d)) * 1024 + hw0 + lane * 4;
            *(float4*)(dst + off) = v;
        } else {
            v.x += bv; v.y += bv; v.z += bv; v.w += bv;
            *(float4*)(Y + ((size_t)slab * 256 + o) * 1024 + hw0 + lane * 4) = v;
        }
    }
}

// ================= split / transpose kernels =================
__global__ __launch_bounds__(256) void split_k(const float* __restrict__ s,
                                               __half* __restrict__ hi,
                                               __half* __restrict__ lo, int n) {
    const int i = blockIdx.x * 256 + threadIdx.x;
    if (i < n) {
        const float f = s[i];
        const __half h = __float2half_rn(f);
        hi[i] = h;
        lo[i] = __float2half_rn(f - __half2float(h));
    }
}

// x [slab][c][hw] f32 -> g_xhi/g_xlo [slab][hw][c] fp16 split (64x64 tiles)
__global__ __launch_bounds__(256) void split_x_k(const float* __restrict__ x) {
    __shared__ float ts[64][65];
    const int slab = blockIdx.z;
    const int c0 = blockIdx.y * 64;
    const int h0 = blockIdx.x * 64;
    const int tid = threadIdx.x;
    const int r = tid >> 2;
    const int q4 = tid & 3;

    const float* src = x + ((size_t)slab * 256 + c0 + r) * 1024 + h0 + q4 * 16;
#pragma unroll
    for (int j = 0; j < 4; j++) {
        const float4 v = *(const float4*)(src + j * 4);
        ts[r][q4 * 16 + j * 4 + 0] = v.x;
        ts[r][q4 * 16 + j * 4 + 1] = v.y;
        ts[r][q4 * 16 + j * 4 + 2] = v.z;
        ts[r][q4 * 16 + j * 4 + 3] = v.w;
    }
    __syncthreads();

    __half hb[16], lb[16];
#pragma unroll
    for (int j = 0; j < 16; j++) {
        const float f = ts[q4 * 16 + j][r];
        const __half h = __float2half_rn(f);
        hb[j] = h;
        lb[j] = __float2half_rn(f - __half2float(h));
    }
    const size_t o = ((size_t)slab * 1024 + h0 + r) * 256 + c0 + q4 * 16;
    *(uint4*)(g_xhi + o)     = ((uint4*)hb)[0];
    *(uint4*)(g_xhi + o + 8) = ((uint4*)hb)[1];
    *(uint4*)(g_xlo + o)     = ((uint4*)lb)[0];
    *(uint4*)(g_xlo + o + 8) = ((uint4*)lb)[1];
}

// ================= attention (T=16), f32 in, fp16-split out =================
__device__ __forceinline__ unsigned long long pack2(float lo, float hi) {
    unsigned long long r;
    asm("mov.b64 %0, {%1, %2};" : "=l"(r) : "f"(lo), "f"(hi));
    return r;
}
__device__ __forceinline__ void unpack2(unsigned long long p, float& lo, float& hi) {
    asm("mov.b64 {%0, %1}, %2;" : "=f"(lo), "=f"(hi) : "l"(p));
}
__device__ __forceinline__ unsigned long long ffma2(unsigned long long a,
                                                    unsigned long long b,
                                                    unsigned long long c) {
    unsigned long long d;
    asm("fma.rn.f32x2 %0, %1, %2, %3;" : "=l"(d) : "l"(a), "l"(b), "l"(c));
    return d;
}

constexpr int KVP = 512 + 4;
__global__ __launch_bounds__(128) void attn_k(const float* __restrict__ rel_pos) {
    __shared__ __align__(16) float k_s[8][KVP];
    __shared__ __align__(16) float v_s[8][KVP];

    const int bh  = blockIdx.y;
    const int hw0 = blockIdx.x * 8;
    const int tid = threadIdx.x;
    const int hwl = tid & 7;
    const int i   = tid >> 3;

    const size_t ubase = (size_t)bh * 512 * HW;

    for (int e = tid; e < 4096; e += 128) {
        const int td = e >> 3;
        const int hw = e & 7;
        k_s[hw][td] = g_k[ubase + (size_t)td * HW + hw0 + hw];
        v_s[hw][td] = g_v[ubase + (size_t)td * HW + hw0 + hw];
    }
    __syncthreads();

    unsigned long long qp[16];
    const size_t qbase = ubase + (size_t)i * 32 * HW + hw0 + hwl;
#pragma unroll
    for (int c = 0; c < 16; c++)
        qp[c] = pack2(g_q[qbase + (size_t)(2 * c) * HW],
                      g_q[qbase + (size_t)(2 * c + 1) * HW]);

    const int head = bh & 7;
    const float* rp = rel_pos + head * 256 + i * 16;

    float s[16];
#pragma unroll
    for (int j = 0; j < 16; j++) {
        const ulonglong2* kp = (const ulonglong2*)&k_s[hwl][j * 32];
        unsigned long long acc = 0ull;
#pragma unroll
        for (int c = 0; c < 8; c++) {
            const ulonglong2 kk = kp[c];
            acc = ffma2(qp[2 * c],     kk.x, acc);
            acc = ffma2(qp[2 * c + 1], kk.y, acc);
        }
        float lo, hi;
        unpack2(acc, lo, hi);
        s[j] = lo + hi + rp[j];
    }

    float mx = s[0];
#pragma unroll
    for (int j = 1; j < 16; j++) mx = fmaxf(mx, s[j]);
    float sum = 0.0f;
#pragma unroll
    for (int j = 0; j < 16; j++) { s[j] = expf(s[j] - mx); sum += s[j]; }
    const float inv = 1.0f / sum;

    unsigned long long o2[16];
#pragma unroll
    for (int c = 0; c < 16; c++) o2[c] = 0ull;
#pragma unroll
    for (int j = 0; j < 16; j++) {
        const unsigned long long pp = pack2(s[j], s[j]);
        const ulonglong2* vp = (const ulonglong2*)&v_s[hwl][j * 32];
#pragma unroll
        for (int c = 0; c < 8; c++) {
            const ulonglong2 vv = vp[c];
            o2[2 * c]     = ffma2(pp, vv.x, o2[2 * c]);
            o2[2 * c + 1] = ffma2(pp, vv.y, o2[2 * c + 1]);
        }
    }

    // write fp16-split output [slab][hw][e]
    const int b_ = bh >> 3;
    const size_t obase =
        ((size_t)((b_ * 16 + i)) * 1024 + hw0 + hwl) * 256 + head * 32;
#pragma unroll
    for (int c = 0; c < 16; c++) {
        float lo, hi;
        unpack2(o2[c], lo, hi);
        const float v0 = lo * inv, v1 = hi * inv;
        const __half h0 = __float2half_rn(v0);
        const __half h1 = __float2half_rn(v1);
        const __half l0 = __float2half_rn(v0 - __half2float(h0));
        const __half l1 = __float2half_rn(v1 - __half2float(h1));
        ((__half2*)(g_ohi + obase))[c] = __halves2half2(h0, h1);
        ((__half2*)(g_olo + obase))[c] = __halves2half2(l0, l1);
    }
}

// ================= host =================
extern "C" void kernel_launch(void* const* d_in, const int* in_sizes, int n_in,
                              void* d_out, int out_size) {
    const float* x       = (const float*)d_in[0];
    const float* rel_pos = (const float*)d_in[1];
    const float* w_qkv   = (const float*)d_in[2];
    const float* b_qkv   = (const float*)d_in[3];
    const float* w_out   = (const float*)d_in[4];
    const float* b_out   = (const float*)d_in[5];
    float* y = (float*)d_out;

    cudaFuncSetAttribute(mma_gemm<0>, cudaFuncAttributeMaxDynamicSharedMemorySize, SMEM_TOTAL);
    cudaFuncSetAttribute(mma_gemm<1>, cudaFuncAttributeMaxDynamicSharedMemorySize, SMEM_TOTAL);

    __half *xhi, *xlo, *whi, *wlo, *wohi, *wolo, *ohi, *olo;
    cudaGetSymbolAddress((void**)&xhi, g_xhi);
    cudaGetSymbolAddress((void**)&xlo, g_xlo);
    cudaGetSymbolAddress((void**)&whi, g_whi);
    cudaGetSymbolAddress((void**)&wlo, g_wlo);
    cudaGetSymbolAddress((void**)&wohi, g_wohi);
    cudaGetSymbolAddress((void**)&wolo, g_wolo);
    cudaGetSymbolAddress((void**)&ohi, g_ohi);
    cudaGetSymbolAddress((void**)&olo, g_olo);

    // precision splits
    split_k<<<768, 256>>>(w_qkv, whi, wlo, 768 * 256);
    split_k<<<256, 256>>>(w_out, wohi, wolo, 256 * 256);
    split_x_k<<<dim3(16, 4, 64), 256>>>(x);

    // QKV projection: grid = (hw tiles 8, o tiles 12, slabs 64)
    mma_gemm<0><<<dim3(8, 12, 64), 128, SMEM_TOTAL>>>(xhi, xlo, whi, wlo, b_qkv, nullptr);
    // attention
    attn_k<<<dim3(128, 32), 128>>>(rel_pos);
    // output projection: grid = (8, 4, 64)
    mma_gemm<1><<<dim3(8, 4, 64), 128, SMEM_TOTAL>>>(ohi, olo, wohi, wolo, b_out, y);
}